// round 2
// baseline (speedup 1.0000x reference)
#include <cuda_runtime.h>
#include <math.h>

#define Bz 16
#define Cc 64
#define Hh 128
#define Ww 128
#define Ee 8
#define HWp (Hh*Ww)
#define EPSV 2.220446049250313e-16f

// ---- device scratch (no allocations allowed) ----
__device__ float g_part[Bz * 32 * Ee];   // per (b, band) logit partials
__device__ int   g_sel[Bz * 2];          // selected expert indices per batch
__device__ float g_w1[Bz];               // 1.0 if second expert's gate > 0, else 0.0

// ============================================================
// Router: conv7x7 (64ch -> 1) + project onto w_gate, per-band partial logits.
// grid (Bz, 32 bands of 4 rows), 128 threads. Each thread: 4 consecutive w pixels.
// ============================================================
__global__ __launch_bounds__(128) void router_kernel(
    const float* __restrict__ x,   // [B,C,H,W]
    const float* __restrict__ rw,  // [1,C,7,7]
    const float* __restrict__ rb,  // [1]
    const float* __restrict__ wg)  // [HW, E]
{
    __shared__ __align__(16) float sT[10 * 136]; // one channel tile, row stride 136 (16B aligned rows)
    __shared__ float sW[49];
    __shared__ float sPart[4][8];

    int b    = blockIdx.x;
    int band = blockIdx.y;
    int h0   = band * 4;
    int t    = threadIdx.x;
    int row  = t >> 5;      // 0..3
    int wq   = t & 31;      // 0..31
    int ws   = wq * 4;

    float r0 = 0.f, r1 = 0.f, r2 = 0.f, r3 = 0.f;

    for (int c = 0; c < Cc; ++c) {
        __syncthreads();
        // load 10x134 halo tile for channel c (zero padded)
        for (int idx = t; idx < 10 * 134; idx += 128) {
            int rr  = idx / 134;
            int col = idx - rr * 134;
            int gh = h0 - 3 + rr;
            int gw = col - 3;
            float v = 0.f;
            if (gh >= 0 && gh < Hh && gw >= 0 && gw < Ww)
                v = x[((b * Cc + c) * Hh + gh) * Ww + gw];
            sT[rr * 136 + col] = v;
        }
        if (t < 49) sW[t] = rw[c * 49 + t];
        __syncthreads();

        #pragma unroll
        for (int dh = 0; dh < 7; ++dh) {
            const float* rp = sT + (row + dh) * 136 + ws;
            float tt[10];
            float4 v0 = *reinterpret_cast<const float4*>(rp);
            float4 v1 = *reinterpret_cast<const float4*>(rp + 4);
            float2 v2 = *reinterpret_cast<const float2*>(rp + 8);
            tt[0]=v0.x; tt[1]=v0.y; tt[2]=v0.z; tt[3]=v0.w;
            tt[4]=v1.x; tt[5]=v1.y; tt[6]=v1.z; tt[7]=v1.w;
            tt[8]=v2.x; tt[9]=v2.y;
            #pragma unroll
            for (int dw = 0; dw < 7; ++dw) {
                float wv = sW[dh * 7 + dw];
                r0 += tt[dw    ] * wv;
                r1 += tt[dw + 1] * wv;
                r2 += tt[dw + 2] * wv;
                r3 += tt[dw + 3] * wv;
            }
        }
    }

    float rbv = rb[0];
    float rv[4] = { r0 + rbv, r1 + rbv, r2 + rbv, r3 + rbv };

    float lacc[8];
    #pragma unroll
    for (int e = 0; e < 8; ++e) lacc[e] = 0.f;
    int h = h0 + row;
    #pragma unroll
    for (int px = 0; px < 4; ++px) {
        int p = h * Ww + ws + px;
        const float4* wp = reinterpret_cast<const float4*>(wg + (long long)p * 8);
        float4 a  = wp[0];
        float4 bb = wp[1];
        float r = rv[px];
        lacc[0] += r * a.x;  lacc[1] += r * a.y;  lacc[2] += r * a.z;  lacc[3] += r * a.w;
        lacc[4] += r * bb.x; lacc[5] += r * bb.y; lacc[6] += r * bb.z; lacc[7] += r * bb.w;
    }

    // reduce 8 accumulators across the block (deterministic)
    int lane = t & 31, warp = t >> 5;
    #pragma unroll
    for (int e = 0; e < 8; ++e) {
        float v = lacc[e];
        #pragma unroll
        for (int off = 16; off; off >>= 1) v += __shfl_down_sync(0xffffffffu, v, off);
        if (lane == 0) sPart[warp][e] = v;
    }
    __syncthreads();
    if (t < 8) {
        float s = sPart[0][t] + sPart[1][t] + sPart[2][t] + sPart[3][t];
        g_part[(b * 32 + band) * 8 + t] = s;
    }
}

// ============================================================
// Gating: reduce partials -> logits, top-2, gates, loss.
// 1 block, 32 threads.
// ============================================================
__global__ void gate_kernel(float* __restrict__ out, long long loss_idx)
{
    __shared__ float imp[8];
    __shared__ int   ldc[8];
    int t = threadIdx.x;
    if (t < 8) { imp[t] = 0.f; ldc[t] = 0; }
    __syncthreads();

    if (t < Bz) {
        float l[8];
        #pragma unroll
        for (int e = 0; e < 8; ++e) {
            float s = 0.f;
            for (int band = 0; band < 32; ++band)
                s += g_part[(t * 32 + band) * 8 + e];
            l[e] = s;
        }
        // top-1 (ties -> lowest index, match lax.top_k stability)
        int i0 = 0; float m0 = l[0];
        #pragma unroll
        for (int e = 1; e < 8; ++e) if (l[e] > m0) { m0 = l[e]; i0 = e; }
        // top-2
        int i1 = (i0 == 0) ? 1 : 0; float m1 = l[i1];
        #pragma unroll
        for (int e = 0; e < 8; ++e) {
            if (e != i0 && l[e] > m1) { m1 = l[e]; i1 = e; }
        }
        float ex = expf(m1 - m0);           // softmax([m0, m1]) stable form
        float g0 = 1.f / (1.f + ex);
        float g1 = ex / (1.f + ex);
        g_sel[t * 2]     = i0;
        g_sel[t * 2 + 1] = i1;
        g_w1[t] = (g1 > 0.f) ? 1.f : 0.f;
        atomicAdd(&imp[i0], g0);
        atomicAdd(&imp[i1], g1);
        atomicAdd(&ldc[i0], 1);
        if (g1 > 0.f) atomicAdd(&ldc[i1], 1);
    }
    __syncthreads();
    if (t == 0) {
        float mi = 0.f, ml = 0.f;
        for (int e = 0; e < 8; ++e) { mi += imp[e]; ml += (float)ldc[e]; }
        mi *= 0.125f; ml *= 0.125f;
        float vi = 0.f, vl = 0.f;
        for (int e = 0; e < 8; ++e) {
            float d  = imp[e] - mi;        vi += d * d;
            float dl = (float)ldc[e] - ml; vl += dl * dl;
        }
        vi *= (1.f / 7.f); vl *= (1.f / 7.f);   // ddof=1
        float loss = (vi / (mi * mi + 1e-10f) + vl / (ml * ml + 1e-10f)) * 0.01f;
        out[loss_idx] = loss;
    }
}

// ============================================================
// Main fused kernel: depthwise 7x7 for shared + 2 selected experts,
// log(exp+exp) combine, add shared, store [B, HW, C] coalesced (lane = c).
// grid (W/32, H/4, B), block (64, 4). Dyn smem: input tile + 3 filters.
// ============================================================
#define RM 4
#define TWm 32
#define INROWS 10
#define INCOLS 38
#define INSTRIDE 381   // 10*38 + 1 (odd -> conflict-free across lane=c)

extern __shared__ float smem_main[];

__global__ __launch_bounds__(256) void main_kernel(
    const float* __restrict__ x,    // [B,C,H,W]
    const float* __restrict__ ew,   // [E,C,1,7,7]
    const float* __restrict__ eb,   // [E,C]
    const float* __restrict__ sw,   // [C,1,7,7]
    const float* __restrict__ sb,   // [C]
    float* __restrict__ out)        // [B,HW,C] (+ loss at the end, not ours)
{
    float* sIn = smem_main;                  // 64 * 381
    float* sWt = smem_main + Cc * INSTRIDE;  // 3 * 3136

    int b  = blockIdx.z;
    int h0 = blockIdx.y * RM;
    int w0 = blockIdx.x * TWm;
    int tid = threadIdx.y * 64 + threadIdx.x;

    int e0  = g_sel[b * 2];
    int e1i = g_sel[b * 2 + 1];
    float w1 = g_w1[b];

    // load input tile: 64 channels x 10 x 38 (zero padded)
    for (int idx = tid; idx < Cc * INROWS * INCOLS; idx += 256) {
        int c   = idx / (INROWS * INCOLS);
        int rem = idx - c * (INROWS * INCOLS);
        int rr  = rem / INCOLS;
        int col = rem - rr * INCOLS;
        int gh = h0 - 3 + rr;
        int gw = w0 - 3 + col;
        float v = 0.f;
        if (gh >= 0 && gh < Hh && gw >= 0 && gw < Ww)
            v = x[((b * Cc + c) * Hh + gh) * Ww + gw];
        sIn[c * INSTRIDE + rr * INCOLS + col] = v;
    }
    // load 3 filters (shared, e0, e1): layout [c*49 + k]
    for (int idx = tid; idx < 3136; idx += 256) {
        sWt[idx]        = sw[idx];
        sWt[3136 + idx] = ew[e0  * 3136 + idx];
        sWt[6272 + idx] = ew[e1i * 3136 + idx];
    }
    __syncthreads();

    int c  = threadIdx.x;
    int ty = threadIdx.y;
    float bS = sb[c];
    float b0 = eb[e0  * Cc + c];
    float b1 = eb[e1i * Cc + c];

    const float* wS  = sWt + c * 49;
    const float* wE0 = sWt + 3136 + c * 49;
    const float* wE1 = sWt + 6272 + c * 49;
    const float* inc = sIn + c * INSTRIDE;

    for (int i = 0; i < 8; ++i) {
        int q   = ty + 4 * i;    // 0..31 quads (4 rows x 8 w-quads)
        int row = q >> 3;
        int wq  = q & 7;
        int wsx = wq * 4;

        float aS[4] = {0,0,0,0};
        float a0[4] = {0,0,0,0};
        float a1[4] = {0,0,0,0};
        const float* inb = inc + row * INCOLS + wsx;

        #pragma unroll
        for (int dh = 0; dh < 7; ++dh) {
            const float* rp = inb + dh * INCOLS;
            float tt[10];
            #pragma unroll
            for (int k = 0; k < 10; ++k) tt[k] = rp[k];
            #pragma unroll
            for (int dw = 0; dw < 7; ++dw) {
                float vS = wS [dh * 7 + dw];
                float v0 = wE0[dh * 7 + dw];
                float v1 = wE1[dh * 7 + dw];
                #pragma unroll
                for (int px = 0; px < 4; ++px) {
                    float tv = tt[px + dw];
                    aS[px] += tv * vS;
                    a0[px] += tv * v0;
                    a1[px] += tv * v1;
                }
            }
        }

        int h = h0 + row;
        long long base = ((long long)(b * HWp + h * Ww + w0 + wsx)) * Cc + c;
        #pragma unroll
        for (int px = 0; px < 4; ++px) {
            float ea  = __expf(a0[px] + b0);
            float ebv = __expf(a1[px] + b1);
            float comb = ea + w1 * ebv;
            comb = (comb == 0.f) ? EPSV : comb;
            out[base + (long long)px * Cc] = __logf(comb) + aS[px] + bS;
        }
    }
}

// ============================================================
extern "C" void kernel_launch(void* const* d_in, const int* in_sizes, int n_in,
                              void* d_out, int out_size) {
    const float* x  = (const float*)d_in[0];
    const float* rw = (const float*)d_in[1];
    const float* rb = (const float*)d_in[2];
    const float* wg = (const float*)d_in[3];
    const float* ew = (const float*)d_in[4];
    const float* eb = (const float*)d_in[5];
    const float* sw = (const float*)d_in[6];
    const float* sb = (const float*)d_in[7];
    float* out = (float*)d_out;

    const int smem_bytes = (Cc * INSTRIDE + 3 * 3136) * (int)sizeof(float); // 135168
    cudaFuncSetAttribute(main_kernel, cudaFuncAttributeMaxDynamicSharedMemorySize, smem_bytes);

    router_kernel<<<dim3(Bz, 32), 128>>>(x, rw, rb, wg);
    gate_kernel<<<1, 32>>>(out, (long long)out_size - 1);
    main_kernel<<<dim3(Ww / TWm, Hh / RM, Bz), dim3(64, 4), smem_bytes>>>(x, ew, eb, sw, sb, out);
}

// round 4
// speedup vs baseline: 1.2843x; 1.2843x over previous
#include <cuda_runtime.h>
#include <math.h>

#define Bz 16
#define Cc 64
#define Hh 128
#define Ww 128
#define HWp (Hh*Ww)
#define EPSV 2.220446049250313e-16f
#define NBAND 16

// ---- device scratch ----
__device__ float g_part[Bz * NBAND * 8];
__device__ int   g_sel[Bz * 2];
__device__ float g_w1[Bz];

typedef unsigned long long u64;

__device__ __forceinline__ u64 pk(float lo, float hi) {
    u64 r; asm("mov.b64 %0, {%1,%2};" : "=l"(r) : "f"(lo), "f"(hi)); return r;
}
__device__ __forceinline__ void upk(u64 v, float& lo, float& hi) {
    asm("mov.b64 {%0,%1}, %2;" : "=f"(lo), "=f"(hi) : "l"(v));
}
__device__ __forceinline__ void fma2(u64& d, u64 a, u64 b) {
    asm("fma.rn.f32x2 %0, %1, %2, %0;" : "+l"(d) : "l"(a), "l"(b));
}

// ============================================================
// Router: conv7x7 (64ch->1) + logits partials. 8-row bands, f32x2,
// double-buffered channel tiles with register prefetch.
// grid (Bz, 16), block 256.
// ============================================================
#define RT_ROWS 14
#define RT_COLS 136
#define RT_ELEM (RT_ROWS * RT_COLS)   // 1904

__global__ __launch_bounds__(256) void router_kernel(
    const float* __restrict__ x,   // [B,C,H,W]
    const float* __restrict__ rw,  // [1,C,7,7]
    const float* __restrict__ rb,  // [1]
    const float* __restrict__ wg)  // [HW, E]
{
    __shared__ float2 sWd[Cc * 49];                         // duplicated weights
    __shared__ __align__(16) float sT[2][RT_ELEM];          // double-buffered tile
    __shared__ float sPart[8][8];

    int b    = blockIdx.x;
    int band = blockIdx.y;
    int h0   = band * 8;
    int t    = threadIdx.x;
    int row  = t >> 5;      // 0..7
    int wq   = t & 31;
    int ws   = wq * 4;

    // preload duplicated router weights
    for (int i = t; i < Cc * 49; i += 256) {
        float w = rw[i];
        sWd[i] = make_float2(w, w);
    }

    const float* xb = x + (long long)b * Cc * HWp;

    float pf[8];
    // prefetch channel 0
    #pragma unroll
    for (int k = 0; k < 8; ++k) {
        int idx = t + k * 256;
        float v = 0.f;
        if (idx < RT_ELEM) {
            int rr  = idx / RT_COLS;
            int col = idx - rr * RT_COLS;
            int gh = h0 - 3 + rr;
            int gw = col - 3;
            if (col < 134 && gh >= 0 && gh < Hh && gw >= 0 && gw < Ww)
                v = xb[gh * Ww + gw];
        }
        pf[k] = v;
    }

    u64 acc01 = pk(0.f, 0.f);
    u64 acc23 = pk(0.f, 0.f);

    for (int c = 0; c < Cc; ++c) {
        int buf = c & 1;
        // store prefetched channel c
        #pragma unroll
        for (int k = 0; k < 8; ++k) {
            int idx = t + k * 256;
            if (idx < RT_ELEM) sT[buf][idx] = pf[k];
        }
        __syncthreads();
        // prefetch channel c+1 (overlaps with compute below)
        if (c + 1 < Cc) {
            const float* xc = xb + (long long)(c + 1) * HWp;
            #pragma unroll
            for (int k = 0; k < 8; ++k) {
                int idx = t + k * 256;
                float v = 0.f;
                if (idx < RT_ELEM) {
                    int rr  = idx / RT_COLS;
                    int col = idx - rr * RT_COLS;
                    int gh = h0 - 3 + rr;
                    int gw = col - 3;
                    if (col < 134 && gh >= 0 && gh < Hh && gw >= 0 && gw < Ww)
                        v = xc[gh * Ww + gw];
                }
                pf[k] = v;
            }
        }
        // compute channel c
        const float* tb = sT[buf];
        const u64* wr = reinterpret_cast<const u64*>(sWd + c * 49);
        #pragma unroll
        for (int dh = 0; dh < 7; ++dh) {
            const float* rp = tb + (row + dh) * RT_COLS + ws;
            float4 v0 = *reinterpret_cast<const float4*>(rp);
            float4 v1 = *reinterpret_cast<const float4*>(rp + 4);
            float2 v2 = *reinterpret_cast<const float2*>(rp + 8);
            float tt[10];
            tt[0]=v0.x; tt[1]=v0.y; tt[2]=v0.z; tt[3]=v0.w;
            tt[4]=v1.x; tt[5]=v1.y; tt[6]=v1.z; tt[7]=v1.w;
            tt[8]=v2.x; tt[9]=v2.y;
            u64 p[9];
            #pragma unroll
            for (int j = 0; j < 9; ++j) p[j] = pk(tt[j], tt[j+1]);
            #pragma unroll
            for (int dw = 0; dw < 7; ++dw) {
                u64 w = wr[dh * 7 + dw];
                fma2(acc01, p[dw],     w);
                fma2(acc23, p[dw + 2], w);
            }
        }
    }

    float rbv = rb[0];
    float rv[4];
    upk(acc01, rv[0], rv[1]);
    upk(acc23, rv[2], rv[3]);
    #pragma unroll
    for (int px = 0; px < 4; ++px) rv[px] += rbv;

    float lacc[8];
    #pragma unroll
    for (int e = 0; e < 8; ++e) lacc[e] = 0.f;
    int h = h0 + row;
    #pragma unroll
    for (int px = 0; px < 4; ++px) {
        int p = h * Ww + ws + px;
        const float4* wp = reinterpret_cast<const float4*>(wg + (long long)p * 8);
        float4 a  = wp[0];
        float4 bb = wp[1];
        float r = rv[px];
        lacc[0] += r * a.x;  lacc[1] += r * a.y;  lacc[2] += r * a.z;  lacc[3] += r * a.w;
        lacc[4] += r * bb.x; lacc[5] += r * bb.y; lacc[6] += r * bb.z; lacc[7] += r * bb.w;
    }

    int lane = t & 31, warp = t >> 5;
    #pragma unroll
    for (int e = 0; e < 8; ++e) {
        float v = lacc[e];
        #pragma unroll
        for (int off = 16; off; off >>= 1) v += __shfl_down_sync(0xffffffffu, v, off);
        if (lane == 0) sPart[warp][e] = v;
    }
    __syncthreads();
    if (t < 8) {
        float s = 0.f;
        #pragma unroll
        for (int w2 = 0; w2 < 8; ++w2) s += sPart[w2][t];
        g_part[(b * NBAND + band) * 8 + t] = s;
    }
}

// ============================================================
// Gating: logits -> top-2 -> gates, deterministic loss.
// 1 block, 32 threads.
// ============================================================
__global__ void gate_kernel(float* __restrict__ out, long long loss_idx)
{
    __shared__ float sg0[Bz], sg1[Bz];
    __shared__ int   si0[Bz], si1[Bz];
    int t = threadIdx.x;

    if (t < Bz) {
        float l[8];
        #pragma unroll
        for (int e = 0; e < 8; ++e) {
            float s = 0.f;
            for (int band = 0; band < NBAND; ++band)
                s += g_part[(t * NBAND + band) * 8 + e];
            l[e] = s;
        }
        int i0 = 0; float m0 = l[0];
        #pragma unroll
        for (int e = 1; e < 8; ++e) if (l[e] > m0) { m0 = l[e]; i0 = e; }
        int i1 = (i0 == 0) ? 1 : 0; float m1 = l[i1];
        #pragma unroll
        for (int e = 0; e < 8; ++e)
            if (e != i0 && l[e] > m1) { m1 = l[e]; i1 = e; }
        float ex = expf(m1 - m0);
        float g0 = 1.f / (1.f + ex);
        float g1 = ex / (1.f + ex);
        g_sel[t * 2]     = i0;
        g_sel[t * 2 + 1] = i1;
        g_w1[t] = (g1 > 0.f) ? 1.f : 0.f;
        si0[t] = i0; si1[t] = i1; sg0[t] = g0; sg1[t] = g1;
    }
    __syncthreads();
    if (t == 0) {
        float imp[8]; float ldc[8];
        #pragma unroll
        for (int e = 0; e < 8; ++e) { imp[e] = 0.f; ldc[e] = 0.f; }
        for (int bb = 0; bb < Bz; ++bb) {           // fixed order: deterministic
            imp[si0[bb]] += sg0[bb];
            imp[si1[bb]] += sg1[bb];
            ldc[si0[bb]] += 1.f;
            if (sg1[bb] > 0.f) ldc[si1[bb]] += 1.f;
        }
        float mi = 0.f, ml = 0.f;
        for (int e = 0; e < 8; ++e) { mi += imp[e]; ml += ldc[e]; }
        mi *= 0.125f; ml *= 0.125f;
        float vi = 0.f, vl = 0.f;
        for (int e = 0; e < 8; ++e) {
            float d  = imp[e] - mi; vi += d * d;
            float dl = ldc[e] - ml; vl += dl * dl;
        }
        vi *= (1.f / 7.f); vl *= (1.f / 7.f);
        float loss = (vi / (mi * mi + 1e-10f) + vl / (ml * ml + 1e-10f)) * 0.01f;
        out[loss_idx] = loss;
    }
}

// ============================================================
// Main fused kernel: 3 depthwise 7x7 convs (shared + 2 experts),
// log(exp+exp) + shared add, f32x2 accumulation, column-strip threads.
// grid (4, 32, 16), block (64, 8). Thread = (channel c, w-quad), all 4 rows.
// ============================================================
#define TIN 404   // channel stride (words): 404 % 4 == 0, 404 % 32 == 20 -> conflict-free LDS.128
#define RIN 40    // row stride (words)
#define INROWS 10

extern __shared__ float smem_main[];

__global__ __launch_bounds__(512) void main_kernel(
    const float* __restrict__ x,    // [B,C,H,W]
    const float* __restrict__ ew,   // [E,C,1,7,7]
    const float* __restrict__ eb,   // [E,C]
    const float* __restrict__ sw,   // [C,1,7,7]
    const float* __restrict__ sb,   // [C]
    float* __restrict__ out)        // [B,HW,C]
{
    float*  sIn = smem_main;                          // 64 * 404 words
    float2* sWd = (float2*)(smem_main + Cc * TIN);    // [3][64][49] duplicated

    int b  = blockIdx.z;
    int h0 = blockIdx.y * 4;
    int w0 = blockIdx.x * 32;
    int tx = threadIdx.x;            // channel
    int ty = threadIdx.y;            // w-quad
    int tid = ty * 64 + tx;

    int e0  = g_sel[b * 2];
    int e1i = g_sel[b * 2 + 1];
    float w1 = g_w1[b];

    const float* xb = x + (long long)b * Cc * HWp;

    // ---- input tile load: 64 ch x 10 rows x 40 cols (38 used) ----
    bool interior = (blockIdx.y >= 1 && blockIdx.y <= 30 &&
                     (blockIdx.x == 1 || blockIdx.x == 2));
    if (interior) {
        const float* xo = xb + (h0 - 3) * Ww + (w0 - 3);
        for (int idx = tid; idx < Cc * INROWS * RIN; idx += 512) {
            int c   = idx / (INROWS * RIN);
            int rem = idx - c * (INROWS * RIN);
            int rr  = rem / RIN;
            int col = rem - rr * RIN;
            sIn[c * TIN + rem] = xo[c * HWp + rr * Ww + col];
        }
    } else {
        for (int idx = tid; idx < Cc * INROWS * RIN; idx += 512) {
            int c   = idx / (INROWS * RIN);
            int rem = idx - c * (INROWS * RIN);
            int rr  = rem / RIN;
            int col = rem - rr * RIN;
            int gh = h0 - 3 + rr;
            int gw = w0 - 3 + col;
            float v = 0.f;
            if (gh >= 0 && gh < Hh && gw >= 0 && gw < Ww)
                v = xb[c * HWp + gh * Ww + gw];
            sIn[c * TIN + rem] = v;
        }
    }
    // ---- duplicated weights: [f][c][49] ----
    for (int idx = tid; idx < 3 * 3136; idx += 512) {
        int f   = idx / 3136;
        int rem = idx - f * 3136;
        float w = (f == 0) ? sw[rem]
                : (f == 1) ? ew[e0  * 3136 + rem]
                           : ew[e1i * 3136 + rem];
        sWd[idx] = make_float2(w, w);
    }
    __syncthreads();

    int c = tx;
    const float* inc = sIn + c * TIN + ty * 4;
    const u64* wB = reinterpret_cast<const u64*>(sWd) + c * 49;  // + f*3136

    u64 acc[3][4][2];
    u64 z = pk(0.f, 0.f);
    #pragma unroll
    for (int f = 0; f < 3; ++f)
        #pragma unroll
        for (int r = 0; r < 4; ++r) { acc[f][r][0] = z; acc[f][r][1] = z; }

    #pragma unroll
    for (int dh = 0; dh < 7; ++dh) {
        u64 wv[3][7];
        #pragma unroll
        for (int f = 0; f < 3; ++f)
            #pragma unroll
            for (int dw = 0; dw < 7; ++dw)
                wv[f][dw] = wB[f * 3136 + dh * 7 + dw];
        #pragma unroll
        for (int r = 0; r < 4; ++r) {
            const float* rp = inc + (r + dh) * RIN;
            float4 v0 = *reinterpret_cast<const float4*>(rp);
            float4 v1 = *reinterpret_cast<const float4*>(rp + 4);
            float2 v2 = *reinterpret_cast<const float2*>(rp + 8);
            float tt[10];
            tt[0]=v0.x; tt[1]=v0.y; tt[2]=v0.z; tt[3]=v0.w;
            tt[4]=v1.x; tt[5]=v1.y; tt[6]=v1.z; tt[7]=v1.w;
            tt[8]=v2.x; tt[9]=v2.y;
            u64 p[9];
            #pragma unroll
            for (int j = 0; j < 9; ++j) p[j] = pk(tt[j], tt[j+1]);
            #pragma unroll
            for (int f = 0; f < 3; ++f)
                #pragma unroll
                for (int dw = 0; dw < 7; ++dw) {
                    fma2(acc[f][r][0], p[dw],     wv[f][dw]);
                    fma2(acc[f][r][1], p[dw + 2], wv[f][dw]);
                }
        }
    }

    // ---- epilogue ----
    float bS = sb[c];
    float b0 = eb[e0  * Cc + c];
    float b1 = eb[e1i * Cc + c];

    #pragma unroll
    for (int r = 0; r < 4; ++r) {
        int h = h0 + r;
        long long base = ((long long)(b * HWp + h * Ww + w0 + ty * 4)) * Cc + c;
        float aS[4], a0[4], a1[4];
        upk(acc[0][r][0], aS[0], aS[1]); upk(acc[0][r][1], aS[2], aS[3]);
        upk(acc[1][r][0], a0[0], a0[1]); upk(acc[1][r][1], a0[2], a0[3]);
        upk(acc[2][r][0], a1[0], a1[1]); upk(acc[2][r][1], a1[2], a1[3]);
        #pragma unroll
        for (int px = 0; px < 4; ++px) {
            float ea  = __expf(a0[px] + b0);
            float ebv = __expf(a1[px] + b1);
            float comb = ea + w1 * ebv;
            comb = (comb == 0.f) ? EPSV : comb;
            out[base + (long long)px * Cc] = __logf(comb) + aS[px] + bS;
        }
    }
}

// ============================================================
extern "C" void kernel_launch(void* const* d_in, const int* in_sizes, int n_in,
                              void* d_out, int out_size) {
    const float* x  = (const float*)d_in[0];
    const float* rw = (const float*)d_in[1];
    const float* rb = (const float*)d_in[2];
    const float* wg = (const float*)d_in[3];
    const float* ew = (const float*)d_in[4];
    const float* eb = (const float*)d_in[5];
    const float* sw = (const float*)d_in[6];
    const float* sb = (const float*)d_in[7];
    float* out = (float*)d_out;

    const int smem_bytes = (Cc * TIN) * 4 + 3 * 3136 * 8;   // 103424 + 75264 = 178688
    cudaFuncSetAttribute(main_kernel, cudaFuncAttributeMaxDynamicSharedMemorySize, smem_bytes);

    router_kernel<<<dim3(Bz, NBAND), 256>>>(x, rw, rb, wg);
    gate_kernel<<<1, 32>>>(out, (long long)out_size - 1);
    main_kernel<<<dim3(Ww / 32, Hh / 4, Bz), dim3(64, 8), smem_bytes>>>(x, ew, eb, sw, sb, out);
}

// round 5
// speedup vs baseline: 1.3271x; 1.0333x over previous
#include <cuda_runtime.h>
#include <math.h>

#define Bz 16
#define Cc 64
#define Hh 128
#define Ww 128
#define HWp (Hh*Ww)
#define EPSV 2.220446049250313e-16f
#define NBAND 16
#define RCG 4            // router channel groups

// ---- device scratch ----
__device__ float g_part[Bz * NBAND * RCG * 8];
__device__ int   g_sel[Bz * 2];
__device__ float g_w1[Bz];

typedef unsigned long long u64;

__device__ __forceinline__ u64 pk(float lo, float hi) {
    u64 r; asm("mov.b64 %0, {%1,%2};" : "=l"(r) : "f"(lo), "f"(hi)); return r;
}
__device__ __forceinline__ void upk(u64 v, float& lo, float& hi) {
    asm("mov.b64 {%0,%1}, %2;" : "=f"(lo), "=f"(hi) : "l"(v));
}
__device__ __forceinline__ void fma2(u64& d, u64 a, u64 b) {
    asm("fma.rn.f32x2 %0, %1, %2, %0;" : "+l"(d) : "l"(a), "l"(b));
}

// ============================================================
// Router: conv7x7 partial over 16 channels + logit partials.
// grid (Bz, NBAND, RCG), block 256. 8-row bands.
// ============================================================
#define RT_ROWS 14
#define RT_COLS 136
#define RT_ELEM (RT_ROWS * RT_COLS)   // 1904
#define RCH 16

__global__ __launch_bounds__(256) void router_kernel(
    const float* __restrict__ x,   // [B,C,H,W]
    const float* __restrict__ rw,  // [1,C,7,7]
    const float* __restrict__ rb,  // [1]
    const float* __restrict__ wg)  // [HW, E]
{
    __shared__ float sW[RCH * 49];
    __shared__ __align__(16) float sT[2][RT_ELEM];
    __shared__ float sPart[8][8];

    int b    = blockIdx.x;
    int band = blockIdx.y;
    int cg   = blockIdx.z;
    int h0   = band * 8;
    int t    = threadIdx.x;
    int row  = t >> 5;      // 0..7
    int wq   = t & 31;
    int ws   = wq * 4;

    for (int i = t; i < RCH * 49; i += 256)
        sW[i] = rw[cg * RCH * 49 + i];

    const float* xb = x + ((long long)b * Cc + cg * RCH) * HWp;

    float pf[8];
    #pragma unroll
    for (int k = 0; k < 8; ++k) {
        int idx = t + k * 256;
        float v = 0.f;
        if (idx < RT_ELEM) {
            int rr  = idx / RT_COLS;
            int col = idx - rr * RT_COLS;
            int gh = h0 - 3 + rr;
            int gw = col - 3;
            if (col < 134 && gh >= 0 && gh < Hh && gw >= 0 && gw < Ww)
                v = xb[gh * Ww + gw];
        }
        pf[k] = v;
    }

    u64 acc01 = pk(0.f, 0.f);
    u64 acc23 = pk(0.f, 0.f);

    for (int c = 0; c < RCH; ++c) {
        int buf = c & 1;
        #pragma unroll
        for (int k = 0; k < 8; ++k) {
            int idx = t + k * 256;
            if (idx < RT_ELEM) sT[buf][idx] = pf[k];
        }
        __syncthreads();
        if (c + 1 < RCH) {
            const float* xc = xb + (long long)(c + 1) * HWp;
            #pragma unroll
            for (int k = 0; k < 8; ++k) {
                int idx = t + k * 256;
                float v = 0.f;
                if (idx < RT_ELEM) {
                    int rr  = idx / RT_COLS;
                    int col = idx - rr * RT_COLS;
                    int gh = h0 - 3 + rr;
                    int gw = col - 3;
                    if (col < 134 && gh >= 0 && gh < Hh && gw >= 0 && gw < Ww)
                        v = xc[gh * Ww + gw];
                }
                pf[k] = v;
            }
        }
        const float* tb = sT[buf];
        const float* wc = sW + c * 49;
        #pragma unroll
        for (int dh = 0; dh < 7; ++dh) {
            // weight pairs built in registers (broadcast LDS.32 + mov.b64)
            u64 w7[7];
            #pragma unroll
            for (int dw = 0; dw < 7; ++dw) {
                float w = wc[dh * 7 + dw];
                w7[dw] = pk(w, w);
            }
            const float* rp = tb + (row + dh) * RT_COLS + ws;
            float4 v0 = *reinterpret_cast<const float4*>(rp);
            float4 v1 = *reinterpret_cast<const float4*>(rp + 4);
            float2 v2 = *reinterpret_cast<const float2*>(rp + 8);
            float tt[10];
            tt[0]=v0.x; tt[1]=v0.y; tt[2]=v0.z; tt[3]=v0.w;
            tt[4]=v1.x; tt[5]=v1.y; tt[6]=v1.z; tt[7]=v1.w;
            tt[8]=v2.x; tt[9]=v2.y;
            u64 p[9];
            #pragma unroll
            for (int j = 0; j < 9; ++j) p[j] = pk(tt[j], tt[j+1]);
            #pragma unroll
            for (int dw = 0; dw < 7; ++dw) {
                fma2(acc01, p[dw],     w7[dw]);
                fma2(acc23, p[dw + 2], w7[dw]);
            }
        }
    }

    float rbv = (cg == 0) ? rb[0] : 0.f;
    float rv[4];
    upk(acc01, rv[0], rv[1]);
    upk(acc23, rv[2], rv[3]);
    #pragma unroll
    for (int px = 0; px < 4; ++px) rv[px] += rbv;

    float lacc[8];
    #pragma unroll
    for (int e = 0; e < 8; ++e) lacc[e] = 0.f;
    int h = h0 + row;
    #pragma unroll
    for (int px = 0; px < 4; ++px) {
        int p = h * Ww + ws + px;
        const float4* wp = reinterpret_cast<const float4*>(wg + (long long)p * 8);
        float4 a  = wp[0];
        float4 bb = wp[1];
        float r = rv[px];
        lacc[0] += r * a.x;  lacc[1] += r * a.y;  lacc[2] += r * a.z;  lacc[3] += r * a.w;
        lacc[4] += r * bb.x; lacc[5] += r * bb.y; lacc[6] += r * bb.z; lacc[7] += r * bb.w;
    }

    int lane = t & 31, warp = t >> 5;
    #pragma unroll
    for (int e = 0; e < 8; ++e) {
        float v = lacc[e];
        #pragma unroll
        for (int off = 16; off; off >>= 1) v += __shfl_down_sync(0xffffffffu, v, off);
        if (lane == 0) sPart[warp][e] = v;
    }
    __syncthreads();
    if (t < 8) {
        float s = 0.f;
        #pragma unroll
        for (int w2 = 0; w2 < 8; ++w2) s += sPart[w2][t];
        g_part[(((b * NBAND) + band) * RCG + cg) * 8 + t] = s;
    }
}

// ============================================================
// Gating: logits -> top-2 -> gates, deterministic loss.
// ============================================================
__global__ void gate_kernel(float* __restrict__ out, long long loss_idx)
{
    __shared__ float sg0[Bz], sg1[Bz];
    __shared__ int   si0[Bz], si1[Bz];
    int t = threadIdx.x;

    if (t < Bz) {
        float l[8];
        #pragma unroll
        for (int e = 0; e < 8; ++e) {
            float s = 0.f;
            for (int k = 0; k < NBAND * RCG; ++k)
                s += g_part[(t * NBAND * RCG + k) * 8 + e];
            l[e] = s;
        }
        int i0 = 0; float m0 = l[0];
        #pragma unroll
        for (int e = 1; e < 8; ++e) if (l[e] > m0) { m0 = l[e]; i0 = e; }
        int i1 = (i0 == 0) ? 1 : 0; float m1 = l[i1];
        #pragma unroll
        for (int e = 0; e < 8; ++e)
            if (e != i0 && l[e] > m1) { m1 = l[e]; i1 = e; }
        float ex = expf(m1 - m0);
        float g0 = 1.f / (1.f + ex);
        float g1 = ex / (1.f + ex);
        g_sel[t * 2]     = i0;
        g_sel[t * 2 + 1] = i1;
        g_w1[t] = (g1 > 0.f) ? 1.f : 0.f;
        si0[t] = i0; si1[t] = i1; sg0[t] = g0; sg1[t] = g1;
    }
    __syncthreads();
    if (t == 0) {
        float imp[8]; float ldc[8];
        #pragma unroll
        for (int e = 0; e < 8; ++e) { imp[e] = 0.f; ldc[e] = 0.f; }
        for (int bb = 0; bb < Bz; ++bb) {
            imp[si0[bb]] += sg0[bb];
            imp[si1[bb]] += sg1[bb];
            ldc[si0[bb]] += 1.f;
            if (sg1[bb] > 0.f) ldc[si1[bb]] += 1.f;
        }
        float mi = 0.f, ml = 0.f;
        for (int e = 0; e < 8; ++e) { mi += imp[e]; ml += ldc[e]; }
        mi *= 0.125f; ml *= 0.125f;
        float vi = 0.f, vl = 0.f;
        for (int e = 0; e < 8; ++e) {
            float d  = imp[e] - mi; vi += d * d;
            float dl = ldc[e] - ml; vl += dl * dl;
        }
        vi *= (1.f / 7.f); vl *= (1.f / 7.f);
        float loss = (vi / (mi * mi + 1e-10f) + vl / (ml * ml + 1e-10f)) * 0.01f;
        out[loss_idx] = loss;
    }
}

// ============================================================
// Main fused kernel v2 (low registers): 32 channels per block.
// grid (4, 32, 32): bz -> (b, cgroup). block (32,16): tx=c, ty=w-pair.
// Thread: 1 channel, 2 px, 4 rows, 3 filters. acc[3][4] u64 = 24 regs.
// ============================================================
#define MCH 32
#define TIN 402   // 402 % 4 == 2 -> LDS.64 8B-aligned for all c; banks 18c mod 32 distinct over 16 lanes
#define RIN 40
#define INROWS 10
#define TILE_ELEM (MCH * INROWS * RIN)   // 12800

extern __shared__ float smem_main[];

__global__ __launch_bounds__(512) void main_kernel(
    const float* __restrict__ x,    // [B,C,H,W]
    const float* __restrict__ ew,   // [E,C,1,7,7]
    const float* __restrict__ eb,   // [E,C]
    const float* __restrict__ sw,   // [C,1,7,7]
    const float* __restrict__ sb,   // [C]
    float* __restrict__ out)        // [B,HW,C]
{
    float* sIn = smem_main;                    // MCH * TIN words
    float* sW  = smem_main + MCH * TIN;        // [3][MCH][49] f32

    int b  = blockIdx.z >> 1;
    int cg = blockIdx.z & 1;
    int h0 = blockIdx.y * 4;
    int w0 = blockIdx.x * 32;
    int tx = threadIdx.x;            // local channel 0..31
    int ty = threadIdx.y;            // w-pair 0..15
    int tid = ty * 32 + tx;

    int e0  = g_sel[b * 2];
    int e1i = g_sel[b * 2 + 1];
    float w1 = g_w1[b];

    const float* xb = x + ((long long)b * Cc + cg * MCH) * HWp;

    // ---- input tile: 32 ch x 10 x 40 ----
    bool interior = (blockIdx.y >= 1 && blockIdx.y <= 30 &&
                     (blockIdx.x == 1 || blockIdx.x == 2));
    if (interior) {
        const float* xo = xb + (h0 - 3) * Ww + (w0 - 3);
        for (int idx = tid; idx < TILE_ELEM; idx += 512) {
            int c   = idx / (INROWS * RIN);
            int rem = idx - c * (INROWS * RIN);
            int rr  = rem / RIN;
            int col = rem - rr * RIN;
            sIn[c * TIN + rem] = xo[c * HWp + rr * Ww + col];
        }
    } else {
        for (int idx = tid; idx < TILE_ELEM; idx += 512) {
            int c   = idx / (INROWS * RIN);
            int rem = idx - c * (INROWS * RIN);
            int rr  = rem / RIN;
            int col = rem - rr * RIN;
            int gh = h0 - 3 + rr;
            int gw = w0 - 3 + col;
            float v = 0.f;
            if (gh >= 0 && gh < Hh && gw >= 0 && gw < Ww)
                v = xb[c * HWp + gh * Ww + gw];
            sIn[c * TIN + rem] = v;
        }
    }
    // ---- weights f32 [f][c][49] ----
    for (int idx = tid; idx < 3 * MCH * 49; idx += 512) {
        int f   = idx / (MCH * 49);
        int rem = idx - f * (MCH * 49);
        int c   = rem / 49;
        int k   = rem - c * 49;
        int gc  = cg * MCH + c;
        float w = (f == 0) ? sw[gc * 49 + k]
                : (f == 1) ? ew[e0  * (Cc * 49) + gc * 49 + k]
                           : ew[e1i * (Cc * 49) + gc * 49 + k];
        sW[idx] = w;
    }
    __syncthreads();

    int c = tx;
    const float* inc = sIn + c * TIN + ty * 2;
    const float* wc  = sW + c * 49;

    u64 acc[3][4];
    u64 z = pk(0.f, 0.f);
    #pragma unroll
    for (int f = 0; f < 3; ++f)
        #pragma unroll
        for (int r = 0; r < 4; ++r) acc[f][r] = z;

    #pragma unroll
    for (int dh = 0; dh < 7; ++dh) {
        u64 wv[3][7];
        #pragma unroll
        for (int f = 0; f < 3; ++f)
            #pragma unroll
            for (int dw = 0; dw < 7; ++dw) {
                float w = wc[f * (MCH * 49) + dh * 7 + dw];
                wv[f][dw] = pk(w, w);
            }
        #pragma unroll
        for (int r = 0; r < 4; ++r) {
            const float* rp = inc + (r + dh) * RIN;
            float2 q0 = *reinterpret_cast<const float2*>(rp);
            float2 q1 = *reinterpret_cast<const float2*>(rp + 2);
            float2 q2 = *reinterpret_cast<const float2*>(rp + 4);
            float2 q3 = *reinterpret_cast<const float2*>(rp + 6);
            float tt[8];
            tt[0]=q0.x; tt[1]=q0.y; tt[2]=q1.x; tt[3]=q1.y;
            tt[4]=q2.x; tt[5]=q2.y; tt[6]=q3.x; tt[7]=q3.y;
            u64 p[7];
            #pragma unroll
            for (int j = 0; j < 7; ++j) p[j] = pk(tt[j], tt[j+1]);
            #pragma unroll
            for (int f = 0; f < 3; ++f)
                #pragma unroll
                for (int dw = 0; dw < 7; ++dw)
                    fma2(acc[f][r], p[dw], wv[f][dw]);
        }
    }

    // ---- epilogue ----
    int gc = cg * MCH + c;
    float bS = sb[gc];
    float b0 = eb[e0  * Cc + gc];
    float b1 = eb[e1i * Cc + gc];

    #pragma unroll
    for (int r = 0; r < 4; ++r) {
        int h = h0 + r;
        long long base = ((long long)(b * HWp + h * Ww + w0 + ty * 2)) * Cc + gc;
        float aS0, aS1, a00, a01, a10, a11;
        upk(acc[0][r], aS0, aS1);
        upk(acc[1][r], a00, a01);
        upk(acc[2][r], a10, a11);
        {
            float ea  = __expf(a00 + b0);
            float ebv = __expf(a10 + b1);
            float comb = ea + w1 * ebv;
            comb = (comb == 0.f) ? EPSV : comb;
            out[base] = __logf(comb) + aS0 + bS;
        }
        {
            float ea  = __expf(a01 + b0);
            float ebv = __expf(a11 + b1);
            float comb = ea + w1 * ebv;
            comb = (comb == 0.f) ? EPSV : comb;
            out[base + Cc] = __logf(comb) + aS1 + bS;
        }
    }
}

// ============================================================
extern "C" void kernel_launch(void* const* d_in, const int* in_sizes, int n_in,
                              void* d_out, int out_size) {
    const float* x  = (const float*)d_in[0];
    const float* rw = (const float*)d_in[1];
    const float* rb = (const float*)d_in[2];
    const float* wg = (const float*)d_in[3];
    const float* ew = (const float*)d_in[4];
    const float* eb = (const float*)d_in[5];
    const float* sw = (const float*)d_in[6];
    const float* sb = (const float*)d_in[7];
    float* out = (float*)d_out;

    const int smem_bytes = (MCH * TIN + 3 * MCH * 49) * (int)sizeof(float); // 51456+18816=70272
    cudaFuncSetAttribute(main_kernel, cudaFuncAttributeMaxDynamicSharedMemorySize, smem_bytes);

    router_kernel<<<dim3(Bz, NBAND, RCG), 256>>>(x, rw, rb, wg);
    gate_kernel<<<1, 32>>>(out, (long long)out_size - 1);
    main_kernel<<<dim3(Ww / 32, Hh / 4, Bz * 2), dim3(32, 16), smem_bytes>>>(x, ew, eb, sw, sb, out);
}